// round 1
// baseline (speedup 1.0000x reference)
#include <cuda_runtime.h>
#include <cuda_bf16.h>

// MIoU (buggy-faithful): answer = popcount(presence mask of classes 1..20 in y_pred) / 21.
// y_true is irrelevant. Presence is monotone -> global 21-bit mask with early exit.

#define FULL_MASK 0x001FFFFEu  // bits 1..20

__device__ unsigned g_mask;

__global__ void k_init() { g_mask = 0u; }

__global__ void __launch_bounds__(256) k_scan(const int4* __restrict__ p, unsigned n4) {
    __shared__ unsigned warp_m[8];
    __shared__ unsigned s_done;

    const unsigned tid    = threadIdx.x;
    const unsigned lane   = tid & 31u;
    const unsigned wid    = tid >> 5;
    const unsigned stride = gridDim.x * blockDim.x;

    // Top check: if the answer is already decided, exit with one L2 read.
    if (tid == 0) s_done = ((__ldcg(&g_mask) & FULL_MASK) == FULL_MASK) ? 1u : 0u;
    __syncthreads();
    if (s_done) return;

    unsigned i = blockIdx.x * blockDim.x + tid;
    const unsigned iters = (n4 + stride - 1u) / stride;
    unsigned m = 0u;

    for (unsigned it = 0; it < iters; ++it, i += stride) {
        if (i < n4) {
            int4 v = __ldcg(&p[i]);   // values are in [0,20]
            m |= (1u << v.x) | (1u << v.y) | (1u << v.z) | (1u << v.w);
        }

        // Block-level completeness check (uniform across the block).
        unsigned wm = __reduce_or_sync(0xffffffffu, m);
        if (lane == 0) warp_m[wid] = wm;
        __syncthreads();
        if (tid == 0) {
            unsigned bm = warp_m[0] | warp_m[1] | warp_m[2] | warp_m[3]
                        | warp_m[4] | warp_m[5] | warp_m[6] | warp_m[7];
            unsigned done = 0u;
            if ((bm & FULL_MASK) == FULL_MASK) {
                // Block saw every class itself: commit (covers all bits we've read) and quit.
                if ((__ldcg(&g_mask) & FULL_MASK) != FULL_MASK)
                    atomicOr(&g_mask, bm);
                done = 1u;
            } else if ((__ldcg(&g_mask) & FULL_MASK) == FULL_MASK) {
                // Answer already fixed globally: our uncommitted bits cannot change it.
                done = 1u;
            }
            s_done = done;
        }
        __syncthreads();
        if (s_done) return;
    }

    // Fallback path (some class absent everywhere): commit what we saw.
    unsigned wm = __reduce_or_sync(0xffffffffu, m);
    if (lane == 0) warp_m[wid] = wm;
    __syncthreads();
    if (tid == 0) {
        unsigned bm = warp_m[0] | warp_m[1] | warp_m[2] | warp_m[3]
                    | warp_m[4] | warp_m[5] | warp_m[6] | warp_m[7];
        if (bm) atomicOr(&g_mask, bm);
    }
}

__global__ void k_final(const int* __restrict__ y, unsigned start, unsigned n,
                        float* __restrict__ out) {
    unsigned m = g_mask;  // prior kernel in stream order; visible
    for (unsigned i = start; i < n; ++i)  // scalar tail (n % 4 elements; here 0)
        m |= 1u << y[i];
    out[0] = (float)__popc(m & FULL_MASK) / 21.0f;
}

extern "C" void kernel_launch(void* const* d_in, const int* in_sizes, int n_in,
                              void* d_out, int out_size) {
    const int* y_pred = (const int*)d_in[0];
    const unsigned n  = (unsigned)in_sizes[0];
    const unsigned n4 = n / 4u;

    k_init<<<1, 1>>>();
    // 1184 = 148 SMs * 8 CTAs: one wave; each block usually does exactly one
    // int4 round (1024 elements) before self-completing.
    k_scan<<<1184, 256>>>((const int4*)y_pred, n4);
    k_final<<<1, 1>>>(y_pred, n4 * 4u, n, (float*)d_out);
}

// round 2
// speedup vs baseline: 1.5556x; 1.5556x over previous
#include <cuda_runtime.h>
#include <cuda_bf16.h>

// MIoU (buggy-faithful): answer = popcount(presence mask of classes 1..20 in y_pred) / 21.
// y_true is irrelevant. Presence is monotone -> per-block early exit after one
// vectorized round; last-block ticket reduction. SINGLE kernel launch (1 graph node).

#define FULL_MASK 0x001FFFFEu  // bits 1..20
#define NBLOCKS   148u
#define NTHREADS  256u

__device__ unsigned g_partial[NBLOCKS];  // overwritten every call — no init needed
__device__ unsigned g_ticket;            // monotone; last-arrival = (t % gridDim == gridDim-1)

__global__ void __launch_bounds__(NTHREADS) k_miou(const int4* __restrict__ p, unsigned n4,
                                                   const int* __restrict__ y, unsigned n,
                                                   float* __restrict__ out) {
    __shared__ unsigned warp_m[NTHREADS / 32];
    __shared__ unsigned s_bm;
    __shared__ unsigned s_last;

    const unsigned tid    = threadIdx.x;
    const unsigned lane   = tid & 31u;
    const unsigned wid    = tid >> 5;
    const unsigned stride = gridDim.x * blockDim.x;

    if (tid == 0) s_bm = 0u;
    __syncthreads();

    unsigned i = blockIdx.x * blockDim.x + tid;
    const unsigned iters = (n4 + stride - 1u) / stride;
    unsigned m = 0u;

    // Scan own slice; block exits as soon as its cumulative mask is complete.
    for (unsigned it = 0; it < iters; ++it, i += stride) {
        if (i < n4) {
            int4 v = __ldcg(&p[i]);  // values in [0,20]
            m |= (1u << v.x) | (1u << v.y) | (1u << v.z) | (1u << v.w);
        }
        unsigned wm = __reduce_or_sync(0xffffffffu, m);
        if (lane == 0) warp_m[wid] = wm;
        __syncthreads();
        if (tid == 0)
            s_bm = warp_m[0] | warp_m[1] | warp_m[2] | warp_m[3]
                 | warp_m[4] | warp_m[5] | warp_m[6] | warp_m[7];
        __syncthreads();
        if ((s_bm & FULL_MASK) == FULL_MASK) break;
    }

    // Publish partial, take a ticket; last arrival of THIS call does the reduce.
    if (tid == 0) {
        __stcg(&g_partial[blockIdx.x], s_bm);
        __threadfence();                          // release: partial visible before ticket
        unsigned t = atomicAdd(&g_ticket, 1u);
        s_last = ((t % gridDim.x) == gridDim.x - 1u) ? 1u : 0u;
    }
    __syncthreads();
    if (!s_last) return;

    __threadfence();                              // acquire side
    unsigned v = (tid < gridDim.x) ? __ldcg(&g_partial[tid]) : 0u;
    // Scalar tail (n % 4 elements; zero for this shape, kept for generality).
    for (unsigned j = n4 * 4u + tid; j < n; j += blockDim.x)
        v |= 1u << __ldcg(&y[j]);

    unsigned wm = __reduce_or_sync(0xffffffffu, v);
    if (lane == 0) warp_m[wid] = wm;
    __syncthreads();
    if (tid == 0) {
        unsigned bm = warp_m[0] | warp_m[1] | warp_m[2] | warp_m[3]
                    | warp_m[4] | warp_m[5] | warp_m[6] | warp_m[7];
        out[0] = (float)__popc(bm & FULL_MASK) / 21.0f;
    }
}

extern "C" void kernel_launch(void* const* d_in, const int* in_sizes, int n_in,
                              void* d_out, int out_size) {
    const int* y_pred = (const int*)d_in[0];
    const unsigned n  = (unsigned)in_sizes[0];
    const unsigned n4 = n / 4u;

    k_miou<<<NBLOCKS, NTHREADS>>>((const int4*)y_pred, n4, y_pred, n, (float*)d_out);
}